// round 2
// baseline (speedup 1.0000x reference)
#include <cuda_runtime.h>
#include <cstdint>

#define NUM_CLASSES 100000
#define FEAT        256
#define BATCH       16384
#define THREADS     256
#define TPS         64                       // threads per sample: 64 * float4 = 256 floats
#define SPB         (THREADS / TPS)          // samples per block = 4
#define NBLK        (BATCH / SPB)            // 4096 blocks
#define F4_PER_ROW  (FEAT / 4)               // 64

// Scratch (device globals — no allocation allowed in kernel_launch).
__device__ float4 g_sums[(size_t)NUM_CLASSES * F4_PER_ROW];   // ~102.4 MB
__device__ int    g_counts[NUM_CLASSES];
__device__ float  g_partials[NBLK];

// ---------------------------------------------------------------------------
// Pass 1: zero only the touched sum rows + counts (duplicates all write zero).
// ---------------------------------------------------------------------------
__global__ __launch_bounds__(THREADS) void zero_touched(const int* __restrict__ label) {
    int gtid = blockIdx.x * THREADS + threadIdx.x;
    int s    = gtid / TPS;
    int lane = gtid % TPS;
    int c = label[s];
    g_sums[(size_t)c * F4_PER_ROW + lane] = make_float4(0.f, 0.f, 0.f, 0.f);
    if (lane == 0) g_counts[c] = 0;
}

// ---------------------------------------------------------------------------
// Pass 2: scatter-accumulate feature sums + counts.
// ---------------------------------------------------------------------------
__global__ __launch_bounds__(THREADS) void accum(const float* __restrict__ x,
                                                 const int* __restrict__ label) {
    int gtid = blockIdx.x * THREADS + threadIdx.x;
    int s    = gtid / TPS;
    int lane = gtid % TPS;
    int c = label[s];

    float4 v = reinterpret_cast<const float4*>(x)[(size_t)s * F4_PER_ROW + lane];
    float* addr = reinterpret_cast<float*>(&g_sums[(size_t)c * F4_PER_ROW + lane]);
    // Vector reduction: one RED op for 16 bytes instead of 4 scalar atomicAdds.
    asm volatile("red.global.add.v4.f32 [%0], {%1, %2, %3, %4};"
                 :: "l"(addr), "f"(v.x), "f"(v.y), "f"(v.z), "f"(v.w)
                 : "memory");
    if (lane == 0) atomicAdd(&g_counts[c], 1);
}

// ---------------------------------------------------------------------------
// Pass 3: per-sample loss contribution; deterministic block reduce.
// ---------------------------------------------------------------------------
__global__ __launch_bounds__(THREADS) void loss_pass(const float* __restrict__ x,
                                                     const int* __restrict__ label,
                                                     const float* __restrict__ center) {
    int gtid = blockIdx.x * THREADS + threadIdx.x;
    int s    = gtid / TPS;
    int lane = gtid % TPS;
    int c = label[s];

    float invn = 1.0f / (float)g_counts[c];   // count >= 1 for any gathered class

    float4 xv = reinterpret_cast<const float4*>(x)[(size_t)s * F4_PER_ROW + lane];
    float4 cv = reinterpret_cast<const float4*>(center)[(size_t)c * F4_PER_ROW + lane];
    float4 sv = g_sums[(size_t)c * F4_PER_ROW + lane];

    float dx = xv.x - (0.99f * cv.x + 0.01f * sv.x * invn);
    float dy = xv.y - (0.99f * cv.y + 0.01f * sv.y * invn);
    float dz = xv.z - (0.99f * cv.z + 0.01f * sv.z * invn);
    float dw = xv.w - (0.99f * cv.w + 0.01f * sv.w * invn);
    float acc = dx * dx + dy * dy + dz * dz + dw * dw;

    // warp reduce (fixed order -> deterministic)
    #pragma unroll
    for (int off = 16; off > 0; off >>= 1)
        acc += __shfl_down_sync(0xFFFFFFFFu, acc, off);

    __shared__ float sh[THREADS / 32];
    int wid = threadIdx.x >> 5;
    if ((threadIdx.x & 31) == 0) sh[wid] = acc;
    __syncthreads();
    if (wid == 0) {
        float a = (threadIdx.x < THREADS / 32) ? sh[threadIdx.x] : 0.f;
        #pragma unroll
        for (int off = 4; off > 0; off >>= 1)
            a += __shfl_down_sync(0xFFFFFFFFu, a, off);
        if (threadIdx.x == 0) g_partials[blockIdx.x] = a;
    }
}

// ---------------------------------------------------------------------------
// Pass 4: deterministic final reduce of 4096 partials -> scalar loss.
// ---------------------------------------------------------------------------
__global__ __launch_bounds__(THREADS) void finalize(float* __restrict__ out) {
    __shared__ float sh[THREADS];
    float a = 0.f;
    for (int i = threadIdx.x; i < NBLK; i += THREADS)
        a += g_partials[i];
    sh[threadIdx.x] = a;
    __syncthreads();
    #pragma unroll
    for (int off = THREADS / 2; off > 0; off >>= 1) {
        if (threadIdx.x < off) sh[threadIdx.x] += sh[threadIdx.x + off];
        __syncthreads();
    }
    if (threadIdx.x == 0)
        out[0] = sh[0] / (float)((long long)BATCH * FEAT);
}

extern "C" void kernel_launch(void* const* d_in, const int* in_sizes, int n_in,
                              void* d_out, int out_size) {
    const float* x      = (const float*)d_in[0];      // batch_feature [16384, 256] f32
    const int*   label  = (const int*)d_in[1];        // batch_label   [16384] int32 (x64 off)
    const float* center = (const float*)d_in[2];      // center_feature[100000, 256] f32
    float* out = (float*)d_out;

    zero_touched<<<NBLK, THREADS>>>(label);
    accum       <<<NBLK, THREADS>>>(x, label);
    loss_pass   <<<NBLK, THREADS>>>(x, label, center);
    finalize    <<<1,    THREADS>>>(out);
}